// round 2
// baseline (speedup 1.0000x reference)
#include <cuda_runtime.h>
#include <math.h>

// Problem constants
#define BB 64
#define JJ 42
#define PP 16384
#define JG 3            // joint groups
#define JT 14           // joints per group (JG*JT == JJ)
#define PC 4            // P chunks
#define PPB (PP/PC)     // 4096 points per block
#define THREADS 256
#define PPT (PPB/THREADS)   // 16 points per thread
#define NWARP (THREADS/32)
#define GRID (BB*JG*PC)     // 768 blocks

// Scratch: per-(b,j) partial min-squared-distance, one slot per P-chunk.
// Layout [(b*JJ+j)][pc] -> float4-loadable per (b,j).
__device__ float g_partial[BB * JJ * PC];
__device__ unsigned int g_count;   // zero at module load; last block resets to 0

typedef unsigned long long u64;

__device__ __forceinline__ u64 pack2(float lo, float hi) {
    u64 r;
    asm("mov.b64 %0, {%1, %2};" : "=l"(r) : "f"(lo), "f"(hi));
    return r;
}
__device__ __forceinline__ void unpack2(u64 v, float& lo, float& hi) {
    asm("mov.b64 {%0, %1}, %2;" : "=f"(lo), "=f"(hi) : "l"(v));
}
__device__ __forceinline__ u64 fma2(u64 a, u64 b, u64 c) {
    u64 d;
    asm("fma.rn.f32x2 %0, %1, %2, %3;" : "=l"(d) : "l"(a), "l"(b), "l"(c));
    return d;
}
__device__ __forceinline__ u64 mul2(u64 a, u64 b) {
    u64 d;
    asm("mul.rn.f32x2 %0, %1, %2;" : "=l"(d) : "l"(a), "l"(b));
    return d;
}

__global__ __launch_bounds__(THREADS) void sdl_fused_kernel(
    const float* __restrict__ pred,   // [B,J,3]
    const float* __restrict__ pts,    // [B,P,3]
    const float* __restrict__ gt,     // [B,J]
    float* __restrict__ out)
{
    const int blk = blockIdx.x;
    const int pc = blk % PC;
    const int jg = (blk / PC) % JG;
    const int b  = blk / (PC * JG);
    const int t  = threadIdx.x;

    // Joint constants in registers, packed for f32x2.
    u64 mx2[JT], my2[JT], mz2[JT];
    float a2[JT], acc[JT];
    const float* jp = pred + (size_t)(b * JJ + jg * JT) * 3;
#pragma unroll
    for (int j = 0; j < JT; j++) {
        float ax = jp[j * 3 + 0];
        float ay = jp[j * 3 + 1];
        float az = jp[j * 3 + 2];
        float mxv = -2.0f * ax, myv = -2.0f * ay, mzv = -2.0f * az;
        mx2[j] = pack2(mxv, mxv);
        my2[j] = pack2(myv, myv);
        mz2[j] = pack2(mzv, mzv);
        a2[j] = fmaf(az, az, fmaf(ay, ay, ax * ax));
        acc[j] = 3.0e38f;
    }

    // Points for this (b, pc): 4096 points via aligned float4 loads.
    const float4* p4 = (const float4*)(pts + ((size_t)b * PP + (size_t)pc * PPB) * 3);

#pragma unroll
    for (int it = 0; it < PPT / 4; it++) {
        const int f4 = it * (THREADS * 3) + t * 3;
        float4 A  = p4[f4 + 0];
        float4 Bv = p4[f4 + 1];
        float4 C  = p4[f4 + 2];

        // 4 points -> 2 packed pairs
        u64 px01 = pack2(A.x,  A.w);
        u64 py01 = pack2(A.y,  Bv.x);
        u64 pz01 = pack2(A.z,  Bv.y);
        u64 px23 = pack2(Bv.z, C.y);
        u64 py23 = pack2(Bv.w, C.z);
        u64 pz23 = pack2(C.x,  C.w);

        u64 b201 = fma2(pz01, pz01, fma2(py01, py01, mul2(px01, px01)));
        u64 b223 = fma2(pz23, pz23, fma2(py23, py23, mul2(px23, px23)));

#pragma unroll
        for (int j = 0; j < JT; j++) {
            u64 t01 = fma2(mx2[j], px01,
                       fma2(my2[j], py01,
                        fma2(mz2[j], pz01, b201)));
            u64 t23 = fma2(mx2[j], px23,
                       fma2(my2[j], py23,
                        fma2(mz2[j], pz23, b223)));
            float l0, h0, l1, h1;
            unpack2(t01, l0, h0);
            unpack2(t23, l1, h1);
            acc[j] = fminf(acc[j], fminf(fminf(l0, h0), fminf(l1, h1)));
        }
    }

    // Fold in |a|^2 (constant shift commutes with min).
#pragma unroll
    for (int j = 0; j < JT; j++) acc[j] += a2[j];

    // Warp min-reduce.
#pragma unroll
    for (int j = 0; j < JT; j++) {
        float v = acc[j];
        v = fminf(v, __shfl_xor_sync(0xFFFFFFFFu, v, 16));
        v = fminf(v, __shfl_xor_sync(0xFFFFFFFFu, v, 8));
        v = fminf(v, __shfl_xor_sync(0xFFFFFFFFu, v, 4));
        v = fminf(v, __shfl_xor_sync(0xFFFFFFFFu, v, 2));
        v = fminf(v, __shfl_xor_sync(0xFFFFFFFFu, v, 1));
        acc[j] = v;
    }

    __shared__ float smin[NWARP][JT];
    const int w = t >> 5, l = t & 31;
    if (l == 0) {
#pragma unroll
        for (int j = 0; j < JT; j++) smin[w][j] = acc[j];
    }
    __syncthreads();

    if (t < JT) {
        float v = smin[0][t];
#pragma unroll
        for (int wi = 1; wi < NWARP; wi++) v = fminf(v, smin[wi][t]);
        g_partial[(size_t)(b * JJ + jg * JT + t) * PC + pc] = v;
    }

    // ---- last-block finalize (fused MSE) ----
    __threadfence();
    __syncthreads();
    __shared__ unsigned s_last;
    if (t == 0) {
        unsigned c = atomicAdd(&g_count, 1u);
        s_last = (c == (unsigned)(GRID - 1)) ? 1u : 0u;
    }
    __syncthreads();
    if (s_last == 0u) return;

    // This is the last block: all partials are globally visible.
    float s = 0.0f;
    const float4* gp = (const float4*)g_partial;
    for (int i = t; i < BB * JJ; i += THREADS) {
        float4 v = __ldcg(gp + i);
        float m = fminf(fminf(v.x, v.y), fminf(v.z, v.w));
        m = fmaxf(m, 0.0f);
        float d = sqrtf(m) - gt[i];
        s = fmaf(d, d, s);
    }
    // Block sum-reduce (fixed order -> deterministic).
    s += __shfl_xor_sync(0xFFFFFFFFu, s, 16);
    s += __shfl_xor_sync(0xFFFFFFFFu, s, 8);
    s += __shfl_xor_sync(0xFFFFFFFFu, s, 4);
    s += __shfl_xor_sync(0xFFFFFFFFu, s, 2);
    s += __shfl_xor_sync(0xFFFFFFFFu, s, 1);
    __shared__ float ssum[NWARP];
    if (l == 0) ssum[w] = s;
    __syncthreads();
    if (t == 0) {
        float tot = ssum[0];
#pragma unroll
        for (int wi = 1; wi < NWARP; wi++) tot += ssum[wi];
        out[0] = tot / (float)(BB * JJ);
        g_count = 0;   // reset for next graph replay
    }
}

extern "C" void kernel_launch(void* const* d_in, const int* in_sizes, int n_in,
                              void* d_out, int out_size) {
    (void)in_sizes; (void)n_in; (void)out_size;
    const float* pred = (const float*)d_in[0];   // [64,42,3]
    const float* pts  = (const float*)d_in[1];   // [64,16384,3]
    const float* gt   = (const float*)d_in[2];   // [64,42]
    float* out = (float*)d_out;

    sdl_fused_kernel<<<GRID, THREADS>>>(pred, pts, gt, out);
}

// round 3
// speedup vs baseline: 1.6611x; 1.6611x over previous
#include <cuda_runtime.h>
#include <math.h>

// Problem constants
#define BB 64
#define JJ 42
#define PP 16384
#define JG 3            // joint groups
#define JT 14           // joints per group (JG*JT == JJ)
#define PC 4            // P chunks
#define PPB (PP/PC)     // 4096 points per block
#define THREADS 256
#define PPT (PPB/THREADS)   // 16 points per thread
#define NWARP (THREADS/32)
#define GRID (BB*JG*PC)     // 768 blocks

// Scratch: per-(b,j) partial min-squared-distance, one slot per P-chunk.
__device__ float g_partial[BB * JJ * PC];
__device__ unsigned int g_count;   // zero at module load; last block resets to 0

__global__ __launch_bounds__(THREADS) void sdl_fused_kernel(
    const float* __restrict__ pred,   // [B,J,3]
    const float* __restrict__ pts,    // [B,P,3]
    const float* __restrict__ gt,     // [B,J]
    float* __restrict__ out)
{
    const int blk = blockIdx.x;
    const int pc = blk % PC;
    const int jg = (blk / PC) % JG;
    const int b  = blk / (PC * JG);
    const int t  = threadIdx.x;

    // Joint constants in registers (uniform across threads).
    float mx[JT], my[JT], mz[JT], a2[JT], acc[JT];
    const float* jp = pred + (size_t)(b * JJ + jg * JT) * 3;
#pragma unroll
    for (int j = 0; j < JT; j++) {
        float ax = jp[j * 3 + 0];
        float ay = jp[j * 3 + 1];
        float az = jp[j * 3 + 2];
        mx[j] = -2.0f * ax;
        my[j] = -2.0f * ay;
        mz[j] = -2.0f * az;
        a2[j] = fmaf(az, az, fmaf(ay, ay, ax * ax));
        acc[j] = 3.0e38f;
    }

    // Points for this (b, pc): 4096 points via aligned float4 loads.
    const float4* p4 = (const float4*)(pts + ((size_t)b * PP + (size_t)pc * PPB) * 3);

#pragma unroll
    for (int it = 0; it < PPT / 4; it++) {
        // 4 points = 12 floats = 3 float4 loads
        const int f4 = it * (THREADS * 3) + t * 3;
        float4 A  = p4[f4 + 0];
        float4 Bv = p4[f4 + 1];
        float4 C  = p4[f4 + 2];

        float px[4], py[4], pz[4], b2[4];
        px[0] = A.x;  py[0] = A.y;  pz[0] = A.z;
        px[1] = A.w;  py[1] = Bv.x; pz[1] = Bv.y;
        px[2] = Bv.z; py[2] = Bv.w; pz[2] = C.x;
        px[3] = C.y;  py[3] = C.z;  pz[3] = C.w;
#pragma unroll
        for (int q = 0; q < 4; q++)
            b2[q] = fmaf(pz[q], pz[q], fmaf(py[q], py[q], px[q] * px[q]));

        // Interleave joints over all 4 points: 4 independent FFMA chains per j.
#pragma unroll
        for (int j = 0; j < JT; j++) {
            float t0 = fmaf(mz[j], pz[0], b2[0]);
            float t1 = fmaf(mz[j], pz[1], b2[1]);
            float t2 = fmaf(mz[j], pz[2], b2[2]);
            float t3 = fmaf(mz[j], pz[3], b2[3]);
            t0 = fmaf(my[j], py[0], t0);
            t1 = fmaf(my[j], py[1], t1);
            t2 = fmaf(my[j], py[2], t2);
            t3 = fmaf(my[j], py[3], t3);
            t0 = fmaf(mx[j], px[0], t0);
            t1 = fmaf(mx[j], px[1], t1);
            t2 = fmaf(mx[j], px[2], t2);
            t3 = fmaf(mx[j], px[3], t3);
            acc[j] = fminf(acc[j], fminf(fminf(t0, t1), fminf(t2, t3)));
        }
    }

    // Fold in |a|^2 (constant shift commutes with min).
#pragma unroll
    for (int j = 0; j < JT; j++) acc[j] += a2[j];

    // Warp min-reduce.
#pragma unroll
    for (int j = 0; j < JT; j++) {
        float v = acc[j];
        v = fminf(v, __shfl_xor_sync(0xFFFFFFFFu, v, 16));
        v = fminf(v, __shfl_xor_sync(0xFFFFFFFFu, v, 8));
        v = fminf(v, __shfl_xor_sync(0xFFFFFFFFu, v, 4));
        v = fminf(v, __shfl_xor_sync(0xFFFFFFFFu, v, 2));
        v = fminf(v, __shfl_xor_sync(0xFFFFFFFFu, v, 1));
        acc[j] = v;
    }

    __shared__ float smin[NWARP][JT];
    const int w = t >> 5, l = t & 31;
    if (l == 0) {
#pragma unroll
        for (int j = 0; j < JT; j++) smin[w][j] = acc[j];
    }
    __syncthreads();

    if (t < JT) {
        float v = smin[0][t];
#pragma unroll
        for (int wi = 1; wi < NWARP; wi++) v = fminf(v, smin[wi][t]);
        g_partial[(size_t)(b * JJ + jg * JT + t) * PC + pc] = v;
    }

    // ---- last-block finalize (fused MSE) ----
    __threadfence();
    __syncthreads();
    __shared__ unsigned s_last;
    if (t == 0) {
        unsigned c = atomicAdd(&g_count, 1u);
        s_last = (c == (unsigned)(GRID - 1)) ? 1u : 0u;
    }
    __syncthreads();
    if (s_last == 0u) return;

    // Last block: all partials globally visible.
    float s = 0.0f;
    const float4* gp = (const float4*)g_partial;
    for (int i = t; i < BB * JJ; i += THREADS) {
        float4 v = __ldcg(gp + i);
        float m = fminf(fminf(v.x, v.y), fminf(v.z, v.w));
        m = fmaxf(m, 0.0f);
        float d = sqrtf(m) - gt[i];
        s = fmaf(d, d, s);
    }
    // Deterministic fixed-order reduction.
    s += __shfl_xor_sync(0xFFFFFFFFu, s, 16);
    s += __shfl_xor_sync(0xFFFFFFFFu, s, 8);
    s += __shfl_xor_sync(0xFFFFFFFFu, s, 4);
    s += __shfl_xor_sync(0xFFFFFFFFu, s, 2);
    s += __shfl_xor_sync(0xFFFFFFFFu, s, 1);
    __shared__ float ssum[NWARP];
    if (l == 0) ssum[w] = s;
    __syncthreads();
    if (t == 0) {
        float tot = ssum[0];
#pragma unroll
        for (int wi = 1; wi < NWARP; wi++) tot += ssum[wi];
        out[0] = tot / (float)(BB * JJ);
        g_count = 0;   // reset for next graph replay
    }
}

extern "C" void kernel_launch(void* const* d_in, const int* in_sizes, int n_in,
                              void* d_out, int out_size) {
    (void)in_sizes; (void)n_in; (void)out_size;
    const float* pred = (const float*)d_in[0];   // [64,42,3]
    const float* pts  = (const float*)d_in[1];   // [64,16384,3]
    const float* gt   = (const float*)d_in[2];   // [64,42]
    float* out = (float*)d_out;

    sdl_fused_kernel<<<GRID, THREADS>>>(pred, pts, gt, out);
}